// round 4
// baseline (speedup 1.0000x reference)
#include <cuda_runtime.h>
#include <math.h>

#define BATCH 4
#define SEQ 8192
#define DIMN 1024
#define RPW 8                 /* rows per warp */
#define WARPS 8
#define RPB 64                /* rows per block */
#define NBB 128               /* blocks per batch (8192/64) */
#define NBLK (BATCH * NBB)    /* 512 */
#define LN_EPS_F 1e-5f
#define FULLMASK 0xffffffffu

// Lookback scratch
__device__ float g_agg[NBLK * DIMN];        // block aggregate (z over 64 rows from 0)
__device__ float g_pref[NBLK * DIMN];       // inclusive prefix (= entry state of next block)
__device__ unsigned g_flag[NBLK];           // 0=none 1=agg 2=prefix
__device__ unsigned g_ticket;

__global__ void mhesa_init() {
    int t = blockIdx.x * blockDim.x + threadIdx.x;
    if (t < NBLK) g_flag[t] = 0u;
    if (t == 0) g_ticket = 0u;
}

__device__ __forceinline__ float4 ldcg_f4(const float* p) {
    float4 v;
    asm volatile("ld.global.cg.v4.f32 {%0,%1,%2,%3}, [%4];"
                 : "=f"(v.x), "=f"(v.y), "=f"(v.z), "=f"(v.w) : "l"(p));
    return v;
}
__device__ __forceinline__ void stcg_f4(float* p, float4 v) {
    asm volatile("st.global.cg.v4.f32 [%0], {%1,%2,%3,%4};"
                 :: "l"(p), "f"(v.x), "f"(v.y), "f"(v.z), "f"(v.w) : "memory");
}

// Single-pass fused LayerNorm + multi-head EMA scan with decoupled lookback.
// Block = 256 threads = 8 warps; warp owns 8 rows x 1024 channels
// (lane covers channels i*128 + lane*4, i = head). z-space: z' = om*z + u,
// out = u*D + (1-om)*z'.
__global__ __launch_bounds__(256, 2) void mhesa_main(
    const float* __restrict__ x, const float* __restrict__ gamma,
    const float* __restrict__ beta, const float* __restrict__ alphas,
    const float* __restrict__ paramD, float* __restrict__ out)
{
    __shared__ float s_g[DIMN], s_b[DIMN], s_d[DIMN];
    __shared__ float s_S[WARPS - 1][DIMN];      // warp-chunk aggregates (warp 7 keeps its own)
    __shared__ float s_E[DIMN];                 // block entry state
    __shared__ float s_inv[RPB], s_nm[RPB];
    __shared__ unsigned s_vbid;

    const int tid = threadIdx.x;
    const int w = tid >> 5, lane = tid & 31;
    const int ch0 = lane * 4;

    if (tid == 0) s_vbid = atomicAdd(&g_ticket, 1u);
    for (int i = tid; i < DIMN; i += 256) {
        s_g[i] = gamma[i]; s_b[i] = beta[i]; s_d[i] = paramD[i];
    }
    __syncthreads();
    const unsigned vbid = s_vbid;               // scheduling-ordered virtual block id
    const int batch = vbid >> 7;
    const int blk = vbid & (NBB - 1);

    float om[8], omC[8];
#pragma unroll
    for (int i = 0; i < 8; i++) {
        float al = __ldg(alphas + i);
        om[i] = 1.0f - 1.0f / (1.0f + expf(-al));
        float o2 = om[i] * om[i], o4 = o2 * o2;
        omC[i] = o4 * o4;                        // om^8 (per warp-chunk decay)
    }

    const size_t rowbase = ((size_t)batch * SEQ + (size_t)blk * RPB + (size_t)w * RPW) * DIMN;

    // ---- Phase 1: LN stats + local z-scan from zero ----
    float4 z[8];
#pragma unroll
    for (int i = 0; i < 8; i++) z[i] = make_float4(0.f, 0.f, 0.f, 0.f);
    {
        const float* xp = x + rowbase + ch0;
        for (int r = 0; r < RPW; r++) {
            float4 xv[8];
            float sum = 0.f, sq = 0.f;
#pragma unroll
            for (int i = 0; i < 8; i++) {
                xv[i] = __ldg((const float4*)(xp + i * 128));
                sum += (xv[i].x + xv[i].y) + (xv[i].z + xv[i].w);
                sq = fmaf(xv[i].x, xv[i].x, sq);
                sq = fmaf(xv[i].y, xv[i].y, sq);
                sq = fmaf(xv[i].z, xv[i].z, sq);
                sq = fmaf(xv[i].w, xv[i].w, sq);
            }
#pragma unroll
            for (int off = 16; off; off >>= 1) {
                sum += __shfl_xor_sync(FULLMASK, sum, off);
                sq  += __shfl_xor_sync(FULLMASK, sq,  off);
            }
            const float mean = sum * (1.0f / (float)DIMN);
            const float var  = fmaf(sq, 1.0f / (float)DIMN, -mean * mean);
            const float inv  = rsqrtf(var + LN_EPS_F);
            const float nm   = -mean * inv;
            if (lane == 0) { s_inv[w * RPW + r] = inv; s_nm[w * RPW + r] = nm; }
#pragma unroll
            for (int i = 0; i < 8; i++) {
                const int ch = i * 128 + ch0;
                const float4 g  = *(const float4*)&s_g[ch];
                const float4 be = *(const float4*)&s_b[ch];
                float4 u;
                u.x = fmaf(fmaf(xv[i].x, inv, nm), g.x, be.x);
                u.y = fmaf(fmaf(xv[i].y, inv, nm), g.y, be.y);
                u.z = fmaf(fmaf(xv[i].z, inv, nm), g.z, be.z);
                u.w = fmaf(fmaf(xv[i].w, inv, nm), g.w, be.w);
                z[i].x = fmaf(om[i], z[i].x, u.x);
                z[i].y = fmaf(om[i], z[i].y, u.y);
                z[i].z = fmaf(om[i], z[i].z, u.z);
                z[i].w = fmaf(om[i], z[i].w, u.w);
            }
            xp += DIMN;
        }
    }
    if (w < 7) {
#pragma unroll
        for (int i = 0; i < 8; i++) *(float4*)&s_S[w][i * 128 + ch0] = z[i];
    }
    __syncthreads();

    // ---- In-block combine: E_local(w) = sum_{w'<w} omC^(w-1-w') * S_w' ----
    float4 el[8];
#pragma unroll
    for (int i = 0; i < 8; i++) el[i] = make_float4(0.f, 0.f, 0.f, 0.f);
    for (int w2 = 0; w2 < w; ++w2) {
#pragma unroll
        for (int i = 0; i < 8; i++) {
            const float4 s = *(const float4*)&s_S[w2][i * 128 + ch0];
            el[i].x = fmaf(omC[i], el[i].x, s.x);
            el[i].y = fmaf(omC[i], el[i].y, s.y);
            el[i].z = fmaf(omC[i], el[i].z, s.z);
            el[i].w = fmaf(omC[i], el[i].w, s.w);
        }
    }

    // ---- Warp 7: block aggregate S_blk = omC*E_local_7 + S_7; publish ----
    float4 sb[8];
    if (w == 7) {
#pragma unroll
        for (int i = 0; i < 8; i++) {
            sb[i].x = fmaf(omC[i], el[i].x, z[i].x);
            sb[i].y = fmaf(omC[i], el[i].y, z[i].y);
            sb[i].z = fmaf(omC[i], el[i].z, z[i].z);
            sb[i].w = fmaf(omC[i], el[i].w, z[i].w);
        }
        if (blk == 0) {
            float* pp = g_pref + (size_t)vbid * DIMN + ch0;
#pragma unroll
            for (int i = 0; i < 8; i++) stcg_f4(pp + i * 128, sb[i]);
            __threadfence(); __syncwarp();
            if (lane == 0) atomicExch(&g_flag[vbid], 2u);
        } else {
            float* ap = g_agg + (size_t)vbid * DIMN + ch0;
#pragma unroll
            for (int i = 0; i < 8; i++) stcg_f4(ap + i * 128, sb[i]);
            __threadfence(); __syncwarp();
            if (lane == 0) atomicExch(&g_flag[vbid], 1u);
        }
    }

    // ---- Warp 0: decoupled lookback over predecessors (same batch) ----
    float4 acc[8];
#pragma unroll
    for (int i = 0; i < 8; i++) acc[i] = make_float4(0.f, 0.f, 0.f, 0.f);
    if (w == 0 && blk > 0) {
        float sc[8], omB[8];
#pragma unroll
        for (int i = 0; i < 8; i++) {
            sc[i] = 1.f;
            float t = omC[i]; t = t * t; t = t * t; t = t * t;   // omC^8 = om^64
            omB[i] = t;
        }
        int j = (int)vbid - 1;
        for (;;) {
            unsigned f = 0;
            if (lane == 0) {
                for (;;) {
                    asm volatile("ld.global.cg.u32 %0, [%1];"
                                 : "=r"(f) : "l"(&g_flag[j]) : "memory");
                    if (f != 0u) break;
                    __nanosleep(32);
                }
            }
            f = __shfl_sync(FULLMASK, f, 0);
            __threadfence();
            const float* sp = (f == 2u ? g_pref : g_agg) + (size_t)j * DIMN + ch0;
#pragma unroll
            for (int i = 0; i < 8; i++) {
                const float4 v = ldcg_f4(sp + i * 128);
                acc[i].x = fmaf(sc[i], v.x, acc[i].x);
                acc[i].y = fmaf(sc[i], v.y, acc[i].y);
                acc[i].z = fmaf(sc[i], v.z, acc[i].z);
                acc[i].w = fmaf(sc[i], v.w, acc[i].w);
            }
            if (f == 2u) break;
#pragma unroll
            for (int i = 0; i < 8; i++) sc[i] *= omB[i];
            --j;
        }
    }
    if (w == 0) {
#pragma unroll
        for (int i = 0; i < 8; i++) *(float4*)&s_E[i * 128 + ch0] = acc[i];
    }
    __syncthreads();

    // ---- Warp 7: publish inclusive prefix = omB*E + S_blk ----
    if (w == 7 && blk > 0) {
        float* pp = g_pref + (size_t)vbid * DIMN + ch0;
#pragma unroll
        for (int i = 0; i < 8; i++) {
            float t = omC[i]; t = t * t; t = t * t; t = t * t;   // om^64
            const float4 e = *(const float4*)&s_E[i * 128 + ch0];
            float4 pv;
            pv.x = fmaf(t, e.x, sb[i].x);
            pv.y = fmaf(t, e.y, sb[i].y);
            pv.z = fmaf(t, e.z, sb[i].z);
            pv.w = fmaf(t, e.w, sb[i].w);
            stcg_f4(pp + i * 128, pv);
        }
        __threadfence(); __syncwarp();
        if (lane == 0) atomicExch(&g_flag[vbid], 2u);
    }

    // ---- Phase 2: seed z = omC^w * E + E_local, replay rows, write out ----
    float4 zz[8];
#pragma unroll
    for (int i = 0; i < 8; i++) {
        float f = 1.f;
        for (int k = 0; k < w; k++) f *= omC[i];
        const float4 e = *(const float4*)&s_E[i * 128 + ch0];
        zz[i].x = fmaf(f, e.x, el[i].x);
        zz[i].y = fmaf(f, e.y, el[i].y);
        zz[i].z = fmaf(f, e.z, el[i].z);
        zz[i].w = fmaf(f, e.w, el[i].w);
    }
    {
        const float* xp = x + rowbase + ch0;
        float* op = out + rowbase + ch0;
        for (int r = 0; r < RPW; r++) {
            const float inv = s_inv[w * RPW + r];
            const float nm  = s_nm[w * RPW + r];
#pragma unroll
            for (int i = 0; i < 8; i++) {
                const int ch = i * 128 + ch0;
                const float4 v  = __ldg((const float4*)(xp + i * 128));  // L1/L2 hit
                const float4 g  = *(const float4*)&s_g[ch];
                const float4 be = *(const float4*)&s_b[ch];
                const float4 d  = *(const float4*)&s_d[ch];
                float4 u;
                u.x = fmaf(fmaf(v.x, inv, nm), g.x, be.x);
                u.y = fmaf(fmaf(v.y, inv, nm), g.y, be.y);
                u.z = fmaf(fmaf(v.z, inv, nm), g.z, be.z);
                u.w = fmaf(fmaf(v.w, inv, nm), g.w, be.w);
                zz[i].x = fmaf(om[i], zz[i].x, u.x);
                zz[i].y = fmaf(om[i], zz[i].y, u.y);
                zz[i].z = fmaf(om[i], zz[i].z, u.z);
                zz[i].w = fmaf(om[i], zz[i].w, u.w);
                const float a = 1.0f - om[i];
                float4 o;
                o.x = fmaf(u.x, d.x, a * zz[i].x);
                o.y = fmaf(u.y, d.y, a * zz[i].y);
                o.z = fmaf(u.z, d.z, a * zz[i].z);
                o.w = fmaf(u.w, d.w, a * zz[i].w);
                __stcs((float4*)(op + i * 128), o);
            }
            xp += DIMN; op += DIMN;
        }
    }
}

extern "C" void kernel_launch(void* const* d_in, const int* in_sizes, int n_in,
                              void* d_out, int out_size)
{
    const float* x      = (const float*)d_in[0];
    const float* gamma  = (const float*)d_in[1];
    const float* beta   = (const float*)d_in[2];
    const float* alphas = (const float*)d_in[3];
    const float* paramD = (const float*)d_in[4];
    float* out = (float*)d_out;

    mhesa_init<<<2, 256>>>();
    mhesa_main<<<NBLK, 256>>>(x, gamma, beta, alphas, paramD, out);
}

// round 5
// speedup vs baseline: 1.8905x; 1.8905x over previous
#include <cuda_runtime.h>
#include <math.h>

#define BATCH 4
#define SEQ 8192
#define DIMN 1024
#define RCH 32                      /* rows per chunk (= per block) */
#define CPB (SEQ / RCH)             /* 256 chunks per batch */
#define NCHT (BATCH * CPB)          /* 1024 chunks total */
#define NSEG 16
#define SEGLEN (CPB / NSEG)         /* 16 */
#define LN_EPS_F 1e-5f
#define FULLMASK 0xffffffffu

// Scratch
__device__ float  g_S[NCHT * DIMN];          // chunk-final local z states (4 MB)
__device__ float  g_P[NCHT * DIMN];          // chunk entry carries (4 MB)
__device__ float  g_A[BATCH * NSEG * DIMN];  // segment aggregates (256 KB)
__device__ float2 g_stats[BATCH * SEQ];      // per-row (inv, nm) (256 KB)

__device__ __forceinline__ float sigm_om(const float* __restrict__ alphas, int head) {
    float al = __ldg(alphas + head);
    return 1.0f - 1.0f / (1.0f + expf(-al));      // om = 1 - sigmoid(alpha)
}
__device__ __forceinline__ float pow32(float om) {
    float t = om * om;  t = t * t;  t = t * t;  t = t * t;  t = t * t;   // om^32
    return t;
}

// ---------------- Pass 1: LN stats + local z-scan per chunk ----------------
// Block = 256 threads; thread owns channels tid*4..tid*4+3 (single head).
// 4-deep register row pipeline; one bar.sync per row (parity smem reduce).
__global__ __launch_bounds__(256, 4) void mhesa_pass1(
    const float* __restrict__ x, const float* __restrict__ gamma,
    const float* __restrict__ beta, const float* __restrict__ alphas)
{
    __shared__ float red[2][16];    // [parity][0..7 sums | 8..15 sqs]

    const int tid = threadIdx.x;
    const int w = tid >> 5, lane = tid & 31;
    const int ch4 = tid * 4;
    const int chunk = blockIdx.x;               // 0..NCHT-1
    const int bat = chunk / CPB;
    const int c = chunk - bat * CPB;

    const float om = sigm_om(alphas, tid >> 5 >> 0 ? (ch4 >> 7) : (ch4 >> 7)); // head = ch4>>7
    const float4 g  = *(const float4*)(gamma + ch4);
    const float4 bb = *(const float4*)(beta + ch4);

    const size_t base = ((size_t)bat * SEQ + (size_t)c * RCH) * DIMN + ch4;
    const int row0 = bat * SEQ + c * RCH;

    float4 buf[4];
#pragma unroll
    for (int k = 0; k < 4; k++)
        buf[k] = __ldg((const float4*)(x + base + (size_t)k * DIMN));

    float4 z = make_float4(0.f, 0.f, 0.f, 0.f);

    for (int rb = 0; rb < RCH; rb += 4) {
#pragma unroll
        for (int k = 0; k < 4; k++) {
            const int r = rb + k;
            const float4 v = buf[k];
            // prefetch row r+4 immediately (keeps 4 loads in flight)
            if (r + 4 < RCH)
                buf[k] = __ldg((const float4*)(x + base + (size_t)(r + 4) * DIMN));
            float sum = (v.x + v.y) + (v.z + v.w);
            float sq  = fmaf(v.x, v.x, fmaf(v.y, v.y, fmaf(v.z, v.z, v.w * v.w)));
#pragma unroll
            for (int off = 16; off; off >>= 1) {
                sum += __shfl_xor_sync(FULLMASK, sum, off);
                sq  += __shfl_xor_sync(FULLMASK, sq,  off);
            }
            const int par = r & 1;
            if (lane == 0) { red[par][w] = sum; red[par][8 + w] = sq; }
            __syncthreads();
            float S = 0.f, Q = 0.f;
#pragma unroll
            for (int j = 0; j < 8; j++) { S += red[par][j]; Q += red[par][8 + j]; }
            const float mean = S * (1.0f / (float)DIMN);
            const float var  = fmaf(Q, 1.0f / (float)DIMN, -mean * mean);
            const float inv  = rsqrtf(var + LN_EPS_F);
            const float nm   = -mean * inv;
            if (tid == 0) g_stats[row0 + r] = make_float2(inv, nm);
            float4 u;
            u.x = fmaf(fmaf(v.x, inv, nm), g.x, bb.x);
            u.y = fmaf(fmaf(v.y, inv, nm), g.y, bb.y);
            u.z = fmaf(fmaf(v.z, inv, nm), g.z, bb.z);
            u.w = fmaf(fmaf(v.w, inv, nm), g.w, bb.w);
            z.x = fmaf(om, z.x, u.x);
            z.y = fmaf(om, z.y, u.y);
            z.z = fmaf(om, z.z, u.z);
            z.w = fmaf(om, z.w, u.w);
        }
    }
    *(float4*)(g_S + (size_t)chunk * DIMN + ch4) = z;
}

// ---------------- Carry phase A: segment aggregates ----------------
// A[b,seg] = sum_j omC^(SEGLEN-1-j) * S[b, seg*SEGLEN + j]
__global__ void mhesa_carryA(const float* __restrict__ alphas)
{
    const int t = blockIdx.x * 256 + threadIdx.x;       // 0..65535
    const int ch = t & (DIMN - 1);
    const int rest = t >> 10;                            // b*NSEG + seg
    const float omC = pow32(sigm_om(alphas, ch >> 7));
    const size_t base = (size_t)rest * SEGLEN * DIMN + ch;
    float s[SEGLEN];
#pragma unroll
    for (int j = 0; j < SEGLEN; j++) s[j] = g_S[base + (size_t)j * DIMN];
    float A = 0.f;
#pragma unroll
    for (int j = 0; j < SEGLEN; j++) A = fmaf(omC, A, s[j]);
    g_A[(size_t)rest * DIMN + ch] = A;
}

// ---------------- Carry phase C: chunk entry carries ----------------
__global__ void mhesa_carryC(const float* __restrict__ alphas)
{
    const int t = blockIdx.x * 256 + threadIdx.x;
    const int ch = t & (DIMN - 1);
    const int rest = t >> 10;
    const int seg = rest & (NSEG - 1);
    const int b = rest >> 4;
    const float omC = pow32(sigm_om(alphas, ch >> 7));
    float omSeg = omC;                                   // omC^SEGLEN = om^512
    omSeg = omSeg * omSeg; omSeg = omSeg * omSeg;
    omSeg = omSeg * omSeg; omSeg = omSeg * omSeg;

    float p = 0.f;
    const size_t abase = (size_t)b * NSEG * DIMN + ch;
    for (int s2 = 0; s2 < seg; s2++)
        p = fmaf(omSeg, p, g_A[abase + (size_t)s2 * DIMN]);

    const size_t base = (size_t)rest * SEGLEN * DIMN + ch;
    float s[SEGLEN];
#pragma unroll
    for (int j = 0; j < SEGLEN; j++) s[j] = g_S[base + (size_t)j * DIMN];
#pragma unroll
    for (int j = 0; j < SEGLEN; j++) {
        g_P[base + (size_t)j * DIMN] = p;
        p = fmaf(omC, p, s[j]);
    }
}

// ---------------- Pass 2: pure stream, no reductions ----------------
// z seeded from g_P; inv/nm loaded from g_stats; out = u*D + a*z.
__global__ __launch_bounds__(256, 4) void mhesa_pass2(
    const float* __restrict__ x, const float* __restrict__ gamma,
    const float* __restrict__ beta, const float* __restrict__ alphas,
    const float* __restrict__ paramD, float* __restrict__ out)
{
    const int tid = threadIdx.x;
    const int ch4 = tid * 4;
    const int chunk = NCHT - 1 - blockIdx.x;    // reverse: reuse pass1's L2 tail
    const int bat = chunk / CPB;
    const int c = chunk - bat * CPB;

    const float om = sigm_om(alphas, ch4 >> 7);
    const float a = 1.0f - om;
    const float4 g  = *(const float4*)(gamma + ch4);
    const float4 bb = *(const float4*)(beta + ch4);
    const float4 d  = *(const float4*)(paramD + ch4);

    const size_t base = ((size_t)bat * SEQ + (size_t)c * RCH) * DIMN + ch4;
    const int row0 = bat * SEQ + c * RCH;

    float4 z = *(const float4*)(g_P + (size_t)chunk * DIMN + ch4);

    float4 buf[4];
#pragma unroll
    for (int k = 0; k < 4; k++)
        buf[k] = __ldg((const float4*)(x + base + (size_t)k * DIMN));

    for (int rb = 0; rb < RCH; rb += 4) {
#pragma unroll
        for (int k = 0; k < 4; k++) {
            const int r = rb + k;
            const float4 v = buf[k];
            if (r + 4 < RCH)
                buf[k] = __ldg((const float4*)(x + base + (size_t)(r + 4) * DIMN));
            const float2 st = __ldg(&g_stats[row0 + r]);   // (inv, nm), warp-broadcast
            const float inv = st.x, nm = st.y;
            float4 u;
            u.x = fmaf(fmaf(v.x, inv, nm), g.x, bb.x);
            u.y = fmaf(fmaf(v.y, inv, nm), g.y, bb.y);
            u.z = fmaf(fmaf(v.z, inv, nm), g.z, bb.z);
            u.w = fmaf(fmaf(v.w, inv, nm), g.w, bb.w);
            z.x = fmaf(om, z.x, u.x);
            z.y = fmaf(om, z.y, u.y);
            z.z = fmaf(om, z.z, u.z);
            z.w = fmaf(om, z.w, u.w);
            float4 o;
            o.x = fmaf(u.x, d.x, a * z.x);
            o.y = fmaf(u.y, d.y, a * z.y);
            o.z = fmaf(u.z, d.z, a * z.z);
            o.w = fmaf(u.w, d.w, a * z.w);
            __stcs((float4*)(out + base + (size_t)r * DIMN), o);
        }
    }
}

extern "C" void kernel_launch(void* const* d_in, const int* in_sizes, int n_in,
                              void* d_out, int out_size)
{
    const float* x      = (const float*)d_in[0];
    const float* gamma  = (const float*)d_in[1];
    const float* beta   = (const float*)d_in[2];
    const float* alphas = (const float*)d_in[3];
    const float* paramD = (const float*)d_in[4];
    float* out = (float*)d_out;

    mhesa_pass1<<<NCHT, 256>>>(x, gamma, beta, alphas);
    mhesa_carryA<<<(BATCH * NSEG * DIMN) / 256, 256>>>(alphas);
    mhesa_carryC<<<(BATCH * NSEG * DIMN) / 256, 256>>>(alphas);
    mhesa_pass2<<<NCHT, 256>>>(x, gamma, beta, alphas, paramD, out);
}